// round 7
// baseline (speedup 1.0000x reference)
#include <cuda_runtime.h>
#include <cuda_bf16.h>

// GCN: 2-layer graph conv, N=100000, E=1.6M, 128 -> 32 -> 32.
// Round 7 (= round 6 resubmitted after infra failure): kernel-count reduction +
// gather0/mid fusion.
//   side stream : gemm1 (feat @ W1 -> g_h, unscaled)
//   main stream : zero -> degrees -> scanA(+norms) -> scanB -> scatter(+blocksums)
//   join        : scale_h (g_h *= norm_out)
//   gather_mid  : [gather t=relu(agg*ni+b1) into smem] + [t@W2*norm_out -> g_h2]
//   gather_out  : d_out = (sum g_h2[src]) * ni + b2

#define MAXN 100000
#define MAXE 1600000
#define SCAN_B 512

__device__ int    g_deg_out[MAXN];
__device__ int    g_deg_in[MAXN];
__device__ float  g_norm_out[MAXN];
__device__ float  g_norm_in[MAXN];
__device__ int    g_offset[MAXN];      // block-local exclusive prefix of deg_in
__device__ int    g_cursor[MAXN];      // scatter cursors
__device__ int    g_csr[MAXE];         // src ids grouped by dst
__device__ int    g_blocksums[(MAXN + SCAN_B - 1) / SCAN_B];
__device__ float4 g_h[MAXN * 8];       // layer-1 projected features (scaled by norm_out)
__device__ float4 g_h2[MAXN * 8];      // layer-2 projected features (scaled by norm_out)

// ---------------------------------------------------------------- zero
__global__ void zero_kernel(int n) {
    int i = blockIdx.x * blockDim.x + threadIdx.x;
    if (i < n) { g_deg_out[i] = 0; g_deg_in[i] = 0; g_cursor[i] = 0; }
}

// ---------------------------------------------------------------- degrees (int)
__global__ void degree_kernel(const int* __restrict__ src,
                              const int* __restrict__ dst, int E) {
    int e = blockIdx.x * blockDim.x + threadIdx.x;
    if (e < E) {
        atomicAdd(&g_deg_out[src[e]], 1);
        atomicAdd(&g_deg_in[dst[e]], 1);
    }
}

// ---------------------------------------------------------------- scanA + norms
// Per-block exclusive scan of deg_in; also computes both norms.
__global__ __launch_bounds__(SCAN_B) void scanA_norm_kernel(int n) {
    __shared__ int swarp[16];
    int t = threadIdx.x;
    int i = blockIdx.x * SCAN_B + t;
    int v = 0;
    if (i < n) {
        int din = g_deg_in[i];
        v = din;
        g_norm_in[i]  = rsqrtf(fmaxf((float)din, 1.f));
        g_norm_out[i] = rsqrtf(fmaxf((float)g_deg_out[i], 1.f));
    }
    int lane = t & 31, w = t >> 5;
    int x = v;
    #pragma unroll
    for (int d = 1; d < 32; d <<= 1) {
        int y = __shfl_up_sync(0xffffffffu, x, d);
        if (lane >= d) x += y;
    }
    if (lane == 31) swarp[w] = x;
    __syncthreads();
    if (w == 0 && t < 16) {
        int y = swarp[t];
        #pragma unroll
        for (int d = 1; d < 16; d <<= 1) {
            int z = __shfl_up_sync(0xffffu, y, d);
            if (t >= d) y += z;
        }
        swarp[t] = y;
    }
    __syncthreads();
    int base = (w > 0) ? swarp[w - 1] : 0;
    int incl = x + base;
    if (i < n) g_offset[i] = incl - v;            // exclusive within block
    if (t == SCAN_B - 1) g_blocksums[blockIdx.x] = incl;
}

// ---------------------------------------------------------------- scanB: scan block sums (nb <= 256)
__global__ __launch_bounds__(256) void scanB_kernel(int nb) {
    __shared__ int swarp[8];
    int t = threadIdx.x;
    int v = (t < nb) ? g_blocksums[t] : 0;
    int lane = t & 31, w = t >> 5;
    int x = v;
    #pragma unroll
    for (int d = 1; d < 32; d <<= 1) {
        int y = __shfl_up_sync(0xffffffffu, x, d);
        if (lane >= d) x += y;
    }
    if (lane == 31) swarp[w] = x;
    __syncthreads();
    if (w == 0 && t < 8) {
        int y = swarp[t];
        #pragma unroll
        for (int d = 1; d < 8; d <<= 1) {
            int z = __shfl_up_sync(0xffu, y, d);
            if (t >= d) y += z;
        }
        swarp[t] = y;
    }
    __syncthreads();
    int base = (w > 0) ? swarp[w - 1] : 0;
    if (t < nb) g_blocksums[t] = x + base - v;    // exclusive
}

// ---------------------------------------------------------------- CSR scatter (blocksums fused)
__global__ void scatter_kernel(const int* __restrict__ src,
                               const int* __restrict__ dst, int E) {
    int e = blockIdx.x * blockDim.x + threadIdx.x;
    if (e < E) {
        int d = dst[e];
        int p = atomicAdd(&g_cursor[d], 1);
        g_csr[g_offset[d] + g_blocksums[d >> 9] + p] = src[e];
    }
}

// ---------------------------------------------------------------- GEMM1 (feat @ W1)
__global__ __launch_bounds__(256) void gemm1_kernel(const float* __restrict__ feat,
                                                    const float* __restrict__ W1, int n) {
    extern __shared__ float4 dyn[];
    float4* sW = dyn;            // [k=128][cg=8]
    float4* sF = dyn + 1024;     // [row=128][k4=32] swizzled
    int t = threadIdx.x;

    for (int i = t; i < 1024; i += 256) sW[i] = ((const float4*)W1)[i];
    int row0 = blockIdx.x * 128;
    #pragma unroll
    for (int j = 0; j < 16; j++) {
        int i = t + j * 256;
        int r = i >> 5, k4 = i & 31;
        int gr = row0 + r;
        float4 v = make_float4(0.f, 0.f, 0.f, 0.f);
        if (gr < n) v = ((const float4*)feat)[gr * 32 + k4];
        sF[r * 32 + (k4 ^ (r & 7))] = v;
    }
    __syncthreads();

    int rt = t >> 3, cg = t & 7;
    int sw = rt & 7;
    const float4* fp0 = &sF[(rt +  0) * 32];
    const float4* fp1 = &sF[(rt + 32) * 32];
    const float4* fp2 = &sF[(rt + 64) * 32];
    const float4* fp3 = &sF[(rt + 96) * 32];

    float4 a0 = make_float4(0.f,0.f,0.f,0.f), a1 = a0, a2 = a0, a3 = a0;

    #pragma unroll 4
    for (int k4 = 0; k4 < 32; k4++) {
        float4 f0 = fp0[k4 ^ sw];
        float4 f1 = fp1[k4 ^ sw];
        float4 f2 = fp2[k4 ^ sw];
        float4 f3 = fp3[k4 ^ sw];
        #pragma unroll
        for (int i = 0; i < 4; i++) {
            float4 w = sW[(k4 * 4 + i) * 8 + cg];
            float c0 = (i == 0) ? f0.x : (i == 1) ? f0.y : (i == 2) ? f0.z : f0.w;
            float c1 = (i == 0) ? f1.x : (i == 1) ? f1.y : (i == 2) ? f1.z : f1.w;
            float c2 = (i == 0) ? f2.x : (i == 1) ? f2.y : (i == 2) ? f2.z : f2.w;
            float c3 = (i == 0) ? f3.x : (i == 1) ? f3.y : (i == 2) ? f3.z : f3.w;
            a0.x += c0*w.x; a0.y += c0*w.y; a0.z += c0*w.z; a0.w += c0*w.w;
            a1.x += c1*w.x; a1.y += c1*w.y; a1.z += c1*w.z; a1.w += c1*w.w;
            a2.x += c2*w.x; a2.y += c2*w.y; a2.z += c2*w.z; a2.w += c2*w.w;
            a3.x += c3*w.x; a3.y += c3*w.y; a3.z += c3*w.z; a3.w += c3*w.w;
        }
    }

    int gr;
    gr = row0 + rt;      if (gr < n) g_h[gr * 8 + cg] = a0;
    gr = row0 + rt + 32; if (gr < n) g_h[gr * 8 + cg] = a1;
    gr = row0 + rt + 64; if (gr < n) g_h[gr * 8 + cg] = a2;
    gr = row0 + rt + 96; if (gr < n) g_h[gr * 8 + cg] = a3;
}

// ---------------------------------------------------------------- scale h by norm_out
__global__ void scale_h_kernel(int n) {
    int i = blockIdx.x * blockDim.x + threadIdx.x;
    if (i >= n * 8) return;
    float s = g_norm_out[i >> 3];
    float4 v = g_h[i];
    v.x *= s; v.y *= s; v.z *= s; v.w *= s;
    g_h[i] = v;
}

// ---------------------------------------------------------------- gather + mid GEMM (fused)
// Phase 1: 8 threads/dst gather t = relu(agg*ni + b1) into smem (128 dsts/block).
// Phase 2: register-blocked t @ W2, epilogue * norm_out -> g_h2.
__global__ __launch_bounds__(256) void gather_mid_kernel(const float* __restrict__ b1,
                                                         const float* __restrict__ W2, int n) {
    __shared__ float4 sW2[32 * 8];    // [k=32][cg=8]
    __shared__ float4 sT[128 * 8];    // [row=128][k4=8] swizzled
    int t = threadIdx.x;
    sW2[t] = ((const float4*)W2)[t];

    int row0 = blockIdx.x * 128;
    int rt = t >> 3, q = t & 7;
    float4 b = ((const float4*)b1)[q];

    #pragma unroll
    for (int jj = 0; jj < 4; jj++) {
        int r = rt + 32 * jj;
        int d = row0 + r;
        float4 acc = make_float4(0.f, 0.f, 0.f, 0.f);
        if (d < n) {
            int j = g_offset[d] + g_blocksums[d >> 9];
            int e = j + g_deg_in[d];
            for (; j + 1 < e; j += 2) {
                int s0 = __ldg(&g_csr[j]);
                int s1 = __ldg(&g_csr[j + 1]);
                float4 v0 = g_h[s0 * 8 + q];
                float4 v1 = g_h[s1 * 8 + q];
                acc.x += v0.x + v1.x;
                acc.y += v0.y + v1.y;
                acc.z += v0.z + v1.z;
                acc.w += v0.w + v1.w;
            }
            if (j < e) {
                int s0 = __ldg(&g_csr[j]);
                float4 v0 = g_h[s0 * 8 + q];
                acc.x += v0.x; acc.y += v0.y; acc.z += v0.z; acc.w += v0.w;
            }
            float ni = g_norm_in[d];
            acc.x = fmaxf(acc.x * ni + b.x, 0.f);
            acc.y = fmaxf(acc.y * ni + b.y, 0.f);
            acc.z = fmaxf(acc.z * ni + b.z, 0.f);
            acc.w = fmaxf(acc.w * ni + b.w, 0.f);
        }
        sT[r * 8 + (q ^ (r & 7))] = acc;
    }
    __syncthreads();

    // GEMM phase: 4 rows/thread, k=32.
    int sw = rt & 7, cg = q;
    const float4* fp0 = &sT[(rt +  0) * 8];
    const float4* fp1 = &sT[(rt + 32) * 8];
    const float4* fp2 = &sT[(rt + 64) * 8];
    const float4* fp3 = &sT[(rt + 96) * 8];

    float4 a0 = make_float4(0.f,0.f,0.f,0.f), a1 = a0, a2 = a0, a3 = a0;

    #pragma unroll
    for (int k4 = 0; k4 < 8; k4++) {
        float4 f0 = fp0[k4 ^ sw];
        float4 f1 = fp1[k4 ^ sw];
        float4 f2 = fp2[k4 ^ sw];
        float4 f3 = fp3[k4 ^ sw];
        #pragma unroll
        for (int i = 0; i < 4; i++) {
            float4 w = sW2[(k4 * 4 + i) * 8 + cg];
            float c0 = (i == 0) ? f0.x : (i == 1) ? f0.y : (i == 2) ? f0.z : f0.w;
            float c1 = (i == 0) ? f1.x : (i == 1) ? f1.y : (i == 2) ? f1.z : f1.w;
            float c2 = (i == 0) ? f2.x : (i == 1) ? f2.y : (i == 2) ? f2.z : f2.w;
            float c3 = (i == 0) ? f3.x : (i == 1) ? f3.y : (i == 2) ? f3.z : f3.w;
            a0.x += c0*w.x; a0.y += c0*w.y; a0.z += c0*w.z; a0.w += c0*w.w;
            a1.x += c1*w.x; a1.y += c1*w.y; a1.z += c1*w.z; a1.w += c1*w.w;
            a2.x += c2*w.x; a2.y += c2*w.y; a2.z += c2*w.z; a2.w += c2*w.w;
            a3.x += c3*w.x; a3.y += c3*w.y; a3.z += c3*w.z; a3.w += c3*w.w;
        }
    }

    #pragma unroll
    for (int j = 0; j < 4; j++) {
        int gr = row0 + rt + 32 * j;
        if (gr < n) {
            float ns = g_norm_out[gr];
            float4 a = (j == 0) ? a0 : (j == 1) ? a1 : (j == 2) ? a2 : a3;
            a.x *= ns; a.y *= ns; a.z *= ns; a.w *= ns;
            g_h2[gr * 8 + cg] = a;
        }
    }
}

// ---------------------------------------------------------------- gather -> output
// out[d] = (sum g_h2[src]) * ni + b2
__global__ __launch_bounds__(256) void gather_out_kernel(const float* __restrict__ b2,
                                                         float4* __restrict__ outp, int n) {
    int tid = blockIdx.x * blockDim.x + threadIdx.x;
    int d = tid >> 3;
    if (d >= n) return;
    int q = tid & 7;
    int j = g_offset[d] + g_blocksums[d >> 9];
    int e = j + g_deg_in[d];

    float4 acc = make_float4(0.f, 0.f, 0.f, 0.f);
    for (; j + 1 < e; j += 2) {
        int s0 = __ldg(&g_csr[j]);
        int s1 = __ldg(&g_csr[j + 1]);
        float4 v0 = g_h2[s0 * 8 + q];
        float4 v1 = g_h2[s1 * 8 + q];
        acc.x += v0.x + v1.x;
        acc.y += v0.y + v1.y;
        acc.z += v0.z + v1.z;
        acc.w += v0.w + v1.w;
    }
    if (j < e) {
        int s0 = __ldg(&g_csr[j]);
        float4 v0 = g_h2[s0 * 8 + q];
        acc.x += v0.x; acc.y += v0.y; acc.z += v0.z; acc.w += v0.w;
    }

    float ni = g_norm_in[d];
    float4 b = ((const float4*)b2)[q];
    acc.x = acc.x * ni + b.x;
    acc.y = acc.y * ni + b.y;
    acc.z = acc.z * ni + b.z;
    acc.w = acc.w * ni + b.w;
    outp[d * 8 + q] = acc;
}

// ---------------------------------------------------------------- launch
namespace {
struct Ctx {
    cudaStream_t side;
    cudaEvent_t eFork, eJoin;
    Ctx() {
        cudaStreamCreateWithFlags(&side, cudaStreamNonBlocking);
        cudaEventCreateWithFlags(&eFork, cudaEventDisableTiming);
        cudaEventCreateWithFlags(&eJoin, cudaEventDisableTiming);
        cudaFuncSetAttribute(gemm1_kernel,
                             cudaFuncAttributeMaxDynamicSharedMemorySize, 81920);
    }
};
}

extern "C" void kernel_launch(void* const* d_in, const int* in_sizes, int n_in,
                              void* d_out, int out_size) {
    static Ctx ctx;   // resource init only (streams/events/attr), no cached work

    const float* feat = (const float*)d_in[0];
    const float* W1   = (const float*)d_in[1];
    const float* b1   = (const float*)d_in[2];
    const float* W2   = (const float*)d_in[3];
    const float* b2   = (const float*)d_in[4];
    const int*   src  = (const int*)d_in[5];
    const int*   dst  = (const int*)d_in[6];
    float4* out = (float4*)d_out;

    int n = in_sizes[0] / 128;
    int E = in_sizes[5];

    const int B = 256;
    int gblocks = (n + 127) / 128;
    int nb = (n + SCAN_B - 1) / SCAN_B;

    // Fork: gemm1 (independent of graph structure) on side stream.
    cudaEventRecord(ctx.eFork, 0);
    cudaStreamWaitEvent(ctx.side, ctx.eFork, 0);
    gemm1_kernel<<<gblocks, 256, 81920, ctx.side>>>(feat, W1, n);
    cudaEventRecord(ctx.eJoin, ctx.side);

    // Main stream: degrees -> scan(+norms) -> CSR (hidden under gemm1).
    zero_kernel     <<<(n + B - 1) / B, B>>>(n);
    degree_kernel   <<<(E + B - 1) / B, B>>>(src, dst, E);
    scanA_norm_kernel<<<nb, SCAN_B>>>(n);
    scanB_kernel    <<<1, 256>>>(nb);
    scatter_kernel  <<<(E + B - 1) / B, B>>>(src, dst, E);

    // Join, then scale h by norm_out.
    cudaStreamWaitEvent(0, ctx.eJoin, 0);
    scale_h_kernel<<<(n * 8 + B - 1) / B, B>>>(n);

    gather_mid_kernel<<<gblocks, 256>>>(b1, W2, n);
    gather_out_kernel<<<(n * 8 + B - 1) / B, B>>>(b2, out, n);
}

// round 8
// speedup vs baseline: 1.0534x; 1.0534x over previous
#include <cuda_runtime.h>
#include <cuda_fp16.h>
#include <cuda_bf16.h>

// GCN: 2-layer graph conv, N=100000, E=1.6M, 128 -> 32 -> 32.
// Round 8: revert gather/mid fusion (round-7 regression), keep fused scans.
// NEW: h / h2 tables stored in FP16 (halves gather L2 traffic); accumulation fp32.
//   side stream : gemm1 (feat @ W1 -> g_hh fp16, unscaled)
//   main stream : zero -> degrees -> scanA(+norms) -> scanB -> scatter
//   join        : scale_h (g_hh *= norm_out, fp32 math)
//   gather0     : g_t = relu((sum g_hh[src]) * ni + b1)   [fp32]
//   mid         : g_hh2 = (g_t @ W2) * norm_out           [fp16 out]
//   gather_out  : d_out = (sum g_hh2[src]) * ni + b2      [fp32 out]

#define MAXN 100000
#define MAXE 1600000
#define SCAN_B 512

__device__ int    g_deg_out[MAXN];
__device__ int    g_deg_in[MAXN];
__device__ float  g_norm_out[MAXN];
__device__ float  g_norm_in[MAXN];
__device__ int    g_offset[MAXN];      // block-local exclusive prefix of deg_in
__device__ int    g_cursor[MAXN];      // scatter cursors
__device__ int    g_csr[MAXE];         // src ids grouped by dst
__device__ int    g_blocksums[(MAXN + SCAN_B - 1) / SCAN_B];
__device__ __half g_hh [MAXN * 32];    // layer-1 projected features (fp16)
__device__ __half g_hh2[MAXN * 32];    // layer-2 projected features (fp16)
__device__ float4 g_t[MAXN * 8];       // layer-1 activations (fp32)

// ---- fp16 pack/unpack helpers (4 halves <-> float4, one 8B access) ----
__device__ __forceinline__ uint2 pack_h4(float4 a) {
    __half2 lo = __floats2half2_rn(a.x, a.y);
    __half2 hi = __floats2half2_rn(a.z, a.w);
    uint2 u;
    u.x = *(const unsigned int*)&lo;
    u.y = *(const unsigned int*)&hi;
    return u;
}
__device__ __forceinline__ float4 unpack_h4(uint2 u) {
    __half2 lo = *(const __half2*)&u.x;
    __half2 hi = *(const __half2*)&u.y;
    float2 f0 = __half22float2(lo);
    float2 f1 = __half22float2(hi);
    return make_float4(f0.x, f0.y, f1.x, f1.y);
}

// ---------------------------------------------------------------- zero
__global__ void zero_kernel(int n) {
    int i = blockIdx.x * blockDim.x + threadIdx.x;
    if (i < n) { g_deg_out[i] = 0; g_deg_in[i] = 0; g_cursor[i] = 0; }
}

// ---------------------------------------------------------------- degrees (int)
__global__ void degree_kernel(const int* __restrict__ src,
                              const int* __restrict__ dst, int E) {
    int e = blockIdx.x * blockDim.x + threadIdx.x;
    if (e < E) {
        atomicAdd(&g_deg_out[src[e]], 1);
        atomicAdd(&g_deg_in[dst[e]], 1);
    }
}

// ---------------------------------------------------------------- scanA + norms
__global__ __launch_bounds__(SCAN_B) void scanA_norm_kernel(int n) {
    __shared__ int swarp[16];
    int t = threadIdx.x;
    int i = blockIdx.x * SCAN_B + t;
    int v = 0;
    if (i < n) {
        int din = g_deg_in[i];
        v = din;
        g_norm_in[i]  = rsqrtf(fmaxf((float)din, 1.f));
        g_norm_out[i] = rsqrtf(fmaxf((float)g_deg_out[i], 1.f));
    }
    int lane = t & 31, w = t >> 5;
    int x = v;
    #pragma unroll
    for (int d = 1; d < 32; d <<= 1) {
        int y = __shfl_up_sync(0xffffffffu, x, d);
        if (lane >= d) x += y;
    }
    if (lane == 31) swarp[w] = x;
    __syncthreads();
    if (w == 0 && t < 16) {
        int y = swarp[t];
        #pragma unroll
        for (int d = 1; d < 16; d <<= 1) {
            int z = __shfl_up_sync(0xffffu, y, d);
            if (t >= d) y += z;
        }
        swarp[t] = y;
    }
    __syncthreads();
    int base = (w > 0) ? swarp[w - 1] : 0;
    int incl = x + base;
    if (i < n) g_offset[i] = incl - v;
    if (t == SCAN_B - 1) g_blocksums[blockIdx.x] = incl;
}

// ---------------------------------------------------------------- scanB (nb <= 256)
__global__ __launch_bounds__(256) void scanB_kernel(int nb) {
    __shared__ int swarp[8];
    int t = threadIdx.x;
    int v = (t < nb) ? g_blocksums[t] : 0;
    int lane = t & 31, w = t >> 5;
    int x = v;
    #pragma unroll
    for (int d = 1; d < 32; d <<= 1) {
        int y = __shfl_up_sync(0xffffffffu, x, d);
        if (lane >= d) x += y;
    }
    if (lane == 31) swarp[w] = x;
    __syncthreads();
    if (w == 0 && t < 8) {
        int y = swarp[t];
        #pragma unroll
        for (int d = 1; d < 8; d <<= 1) {
            int z = __shfl_up_sync(0xffu, y, d);
            if (t >= d) y += z;
        }
        swarp[t] = y;
    }
    __syncthreads();
    int base = (w > 0) ? swarp[w - 1] : 0;
    if (t < nb) g_blocksums[t] = x + base - v;
}

// ---------------------------------------------------------------- CSR scatter
__global__ void scatter_kernel(const int* __restrict__ src,
                               const int* __restrict__ dst, int E) {
    int e = blockIdx.x * blockDim.x + threadIdx.x;
    if (e < E) {
        int d = dst[e];
        int p = atomicAdd(&g_cursor[d], 1);
        g_csr[g_offset[d] + g_blocksums[d >> 9] + p] = src[e];
    }
}

// ---------------------------------------------------------------- GEMM1 (feat @ W1 -> fp16)
__global__ __launch_bounds__(256) void gemm1_kernel(const float* __restrict__ feat,
                                                    const float* __restrict__ W1, int n) {
    extern __shared__ float4 dyn[];
    float4* sW = dyn;            // [k=128][cg=8]
    float4* sF = dyn + 1024;     // [row=128][k4=32] swizzled
    int t = threadIdx.x;

    for (int i = t; i < 1024; i += 256) sW[i] = ((const float4*)W1)[i];
    int row0 = blockIdx.x * 128;
    #pragma unroll
    for (int j = 0; j < 16; j++) {
        int i = t + j * 256;
        int r = i >> 5, k4 = i & 31;
        int gr = row0 + r;
        float4 v = make_float4(0.f, 0.f, 0.f, 0.f);
        if (gr < n) v = ((const float4*)feat)[gr * 32 + k4];
        sF[r * 32 + (k4 ^ (r & 7))] = v;
    }
    __syncthreads();

    int rt = t >> 3, cg = t & 7;
    int sw = rt & 7;
    const float4* fp0 = &sF[(rt +  0) * 32];
    const float4* fp1 = &sF[(rt + 32) * 32];
    const float4* fp2 = &sF[(rt + 64) * 32];
    const float4* fp3 = &sF[(rt + 96) * 32];

    float4 a0 = make_float4(0.f,0.f,0.f,0.f), a1 = a0, a2 = a0, a3 = a0;

    #pragma unroll 4
    for (int k4 = 0; k4 < 32; k4++) {
        float4 f0 = fp0[k4 ^ sw];
        float4 f1 = fp1[k4 ^ sw];
        float4 f2 = fp2[k4 ^ sw];
        float4 f3 = fp3[k4 ^ sw];
        #pragma unroll
        for (int i = 0; i < 4; i++) {
            float4 w = sW[(k4 * 4 + i) * 8 + cg];
            float c0 = (i == 0) ? f0.x : (i == 1) ? f0.y : (i == 2) ? f0.z : f0.w;
            float c1 = (i == 0) ? f1.x : (i == 1) ? f1.y : (i == 2) ? f1.z : f1.w;
            float c2 = (i == 0) ? f2.x : (i == 1) ? f2.y : (i == 2) ? f2.z : f2.w;
            float c3 = (i == 0) ? f3.x : (i == 1) ? f3.y : (i == 2) ? f3.z : f3.w;
            a0.x += c0*w.x; a0.y += c0*w.y; a0.z += c0*w.z; a0.w += c0*w.w;
            a1.x += c1*w.x; a1.y += c1*w.y; a1.z += c1*w.z; a1.w += c1*w.w;
            a2.x += c2*w.x; a2.y += c2*w.y; a2.z += c2*w.z; a2.w += c2*w.w;
            a3.x += c3*w.x; a3.y += c3*w.y; a3.z += c3*w.z; a3.w += c3*w.w;
        }
    }

    int gr;
    gr = row0 + rt;      if (gr < n) *(uint2*)&g_hh[gr * 32 + cg * 4] = pack_h4(a0);
    gr = row0 + rt + 32; if (gr < n) *(uint2*)&g_hh[gr * 32 + cg * 4] = pack_h4(a1);
    gr = row0 + rt + 64; if (gr < n) *(uint2*)&g_hh[gr * 32 + cg * 4] = pack_h4(a2);
    gr = row0 + rt + 96; if (gr < n) *(uint2*)&g_hh[gr * 32 + cg * 4] = pack_h4(a3);
}

// ---------------------------------------------------------------- scale h by norm_out (fp16 in/out)
__global__ void scale_h_kernel(int n) {
    int i = blockIdx.x * blockDim.x + threadIdx.x;   // one uint2 (4 halves) per thread
    if (i >= n * 8) return;
    float s = g_norm_out[i >> 3];
    float4 v = unpack_h4(*(const uint2*)&g_hh[i * 4]);
    v.x *= s; v.y *= s; v.z *= s; v.w *= s;
    *(uint2*)&g_hh[i * 4] = pack_h4(v);
}

// ---------------------------------------------------------------- gather0
// 8 threads/dst; acc = sum g_hh[src] (fp32 accum); g_t = relu(acc*ni + b1).
__global__ __launch_bounds__(256) void gather0_kernel(const float* __restrict__ b1, int n) {
    int tid = blockIdx.x * blockDim.x + threadIdx.x;
    int d = tid >> 3;
    if (d >= n) return;
    int q = tid & 7;
    int j = g_offset[d] + g_blocksums[d >> 9];
    int e = j + g_deg_in[d];

    float4 acc = make_float4(0.f, 0.f, 0.f, 0.f);
    for (; j + 3 < e; j += 4) {
        int s0 = __ldg(&g_csr[j]);
        int s1 = __ldg(&g_csr[j + 1]);
        int s2 = __ldg(&g_csr[j + 2]);
        int s3 = __ldg(&g_csr[j + 3]);
        float4 v0 = unpack_h4(*(const uint2*)&g_hh[s0 * 32 + q * 4]);
        float4 v1 = unpack_h4(*(const uint2*)&g_hh[s1 * 32 + q * 4]);
        float4 v2 = unpack_h4(*(const uint2*)&g_hh[s2 * 32 + q * 4]);
        float4 v3 = unpack_h4(*(const uint2*)&g_hh[s3 * 32 + q * 4]);
        acc.x += (v0.x + v1.x) + (v2.x + v3.x);
        acc.y += (v0.y + v1.y) + (v2.y + v3.y);
        acc.z += (v0.z + v1.z) + (v2.z + v3.z);
        acc.w += (v0.w + v1.w) + (v2.w + v3.w);
    }
    for (; j < e; j++) {
        int s0 = __ldg(&g_csr[j]);
        float4 v0 = unpack_h4(*(const uint2*)&g_hh[s0 * 32 + q * 4]);
        acc.x += v0.x; acc.y += v0.y; acc.z += v0.z; acc.w += v0.w;
    }

    float ni = g_norm_in[d];
    float4 b = ((const float4*)b1)[q];
    acc.x = fmaxf(acc.x * ni + b.x, 0.f);
    acc.y = fmaxf(acc.y * ni + b.y, 0.f);
    acc.z = fmaxf(acc.z * ni + b.z, 0.f);
    acc.w = fmaxf(acc.w * ni + b.w, 0.f);
    g_t[d * 8 + q] = acc;
}

// ---------------------------------------------------------------- mid GEMM (g_t @ W2 -> fp16)
__global__ __launch_bounds__(256) void mid_kernel(const float* __restrict__ W2, int n) {
    __shared__ float4 sW2[32 * 8];
    __shared__ float4 sT[128 * 8];
    int t = threadIdx.x;
    sW2[t] = ((const float4*)W2)[t];
    int row0 = blockIdx.x * 128;
    #pragma unroll
    for (int j = 0; j < 4; j++) {
        int i = t + j * 256;
        int r = i >> 3, k4 = i & 7;
        int gr = row0 + r;
        float4 v = make_float4(0.f, 0.f, 0.f, 0.f);
        if (gr < n) v = g_t[gr * 8 + k4];
        sT[r * 8 + (k4 ^ (r & 7))] = v;
    }
    __syncthreads();

    int rt = t >> 3, cg = t & 7;
    int sw = rt & 7;
    const float4* fp0 = &sT[(rt +  0) * 8];
    const float4* fp1 = &sT[(rt + 32) * 8];
    const float4* fp2 = &sT[(rt + 64) * 8];
    const float4* fp3 = &sT[(rt + 96) * 8];

    float4 a0 = make_float4(0.f,0.f,0.f,0.f), a1 = a0, a2 = a0, a3 = a0;

    #pragma unroll
    for (int k4 = 0; k4 < 8; k4++) {
        float4 f0 = fp0[k4 ^ sw];
        float4 f1 = fp1[k4 ^ sw];
        float4 f2 = fp2[k4 ^ sw];
        float4 f3 = fp3[k4 ^ sw];
        #pragma unroll
        for (int i = 0; i < 4; i++) {
            float4 w = sW2[(k4 * 4 + i) * 8 + cg];
            float c0 = (i == 0) ? f0.x : (i == 1) ? f0.y : (i == 2) ? f0.z : f0.w;
            float c1 = (i == 0) ? f1.x : (i == 1) ? f1.y : (i == 2) ? f1.z : f1.w;
            float c2 = (i == 0) ? f2.x : (i == 1) ? f2.y : (i == 2) ? f2.z : f2.w;
            float c3 = (i == 0) ? f3.x : (i == 1) ? f3.y : (i == 2) ? f3.z : f3.w;
            a0.x += c0*w.x; a0.y += c0*w.y; a0.z += c0*w.z; a0.w += c0*w.w;
            a1.x += c1*w.x; a1.y += c1*w.y; a1.z += c1*w.z; a1.w += c1*w.w;
            a2.x += c2*w.x; a2.y += c2*w.y; a2.z += c2*w.z; a2.w += c2*w.w;
            a3.x += c3*w.x; a3.y += c3*w.y; a3.z += c3*w.z; a3.w += c3*w.w;
        }
    }

    #pragma unroll
    for (int j = 0; j < 4; j++) {
        int gr = row0 + rt + 32 * j;
        if (gr < n) {
            float ns = g_norm_out[gr];
            float4 a = (j == 0) ? a0 : (j == 1) ? a1 : (j == 2) ? a2 : a3;
            a.x *= ns; a.y *= ns; a.z *= ns; a.w *= ns;
            *(uint2*)&g_hh2[gr * 32 + cg * 4] = pack_h4(a);
        }
    }
}

// ---------------------------------------------------------------- gather -> output (fp32)
__global__ __launch_bounds__(256) void gather_out_kernel(const float* __restrict__ b2,
                                                         float4* __restrict__ outp, int n) {
    int tid = blockIdx.x * blockDim.x + threadIdx.x;
    int d = tid >> 3;
    if (d >= n) return;
    int q = tid & 7;
    int j = g_offset[d] + g_blocksums[d >> 9];
    int e = j + g_deg_in[d];

    float4 acc = make_float4(0.f, 0.f, 0.f, 0.f);
    for (; j + 3 < e; j += 4) {
        int s0 = __ldg(&g_csr[j]);
        int s1 = __ldg(&g_csr[j + 1]);
        int s2 = __ldg(&g_csr[j + 2]);
        int s3 = __ldg(&g_csr[j + 3]);
        float4 v0 = unpack_h4(*(const uint2*)&g_hh2[s0 * 32 + q * 4]);
        float4 v1 = unpack_h4(*(const uint2*)&g_hh2[s1 * 32 + q * 4]);
        float4 v2 = unpack_h4(*(const uint2*)&g_hh2[s2 * 32 + q * 4]);
        float4 v3 = unpack_h4(*(const uint2*)&g_hh2[s3 * 32 + q * 4]);
        acc.x += (v0.x + v1.x) + (v2.x + v3.x);
        acc.y += (v0.y + v1.y) + (v2.y + v3.y);
        acc.z += (v0.z + v1.z) + (v2.z + v3.z);
        acc.w += (v0.w + v1.w) + (v2.w + v3.w);
    }
    for (; j < e; j++) {
        int s0 = __ldg(&g_csr[j]);
        float4 v0 = unpack_h4(*(const uint2*)&g_hh2[s0 * 32 + q * 4]);
        acc.x += v0.x; acc.y += v0.y; acc.z += v0.z; acc.w += v0.w;
    }

    float ni = g_norm_in[d];
    float4 b = ((const float4*)b2)[q];
    acc.x = acc.x * ni + b.x;
    acc.y = acc.y * ni + b.y;
    acc.z = acc.z * ni + b.z;
    acc.w = acc.w * ni + b.w;
    outp[d * 8 + q] = acc;
}

// ---------------------------------------------------------------- launch
namespace {
struct Ctx {
    cudaStream_t side;
    cudaEvent_t eFork, eJoin;
    Ctx() {
        cudaStreamCreateWithFlags(&side, cudaStreamNonBlocking);
        cudaEventCreateWithFlags(&eFork, cudaEventDisableTiming);
        cudaEventCreateWithFlags(&eJoin, cudaEventDisableTiming);
        cudaFuncSetAttribute(gemm1_kernel,
                             cudaFuncAttributeMaxDynamicSharedMemorySize, 81920);
    }
};
}

extern "C" void kernel_launch(void* const* d_in, const int* in_sizes, int n_in,
                              void* d_out, int out_size) {
    static Ctx ctx;   // resource init only (streams/events/attr), no cached work

    const float* feat = (const float*)d_in[0];
    const float* W1   = (const float*)d_in[1];
    const float* b1   = (const float*)d_in[2];
    const float* W2   = (const float*)d_in[3];
    const float* b2   = (const float*)d_in[4];
    const int*   src  = (const int*)d_in[5];
    const int*   dst  = (const int*)d_in[6];
    float4* out = (float4*)d_out;

    int n = in_sizes[0] / 128;
    int E = in_sizes[5];

    const int B = 256;
    int gblocks = (n + 127) / 128;
    int nb = (n + SCAN_B - 1) / SCAN_B;

    // Fork: gemm1 (independent of graph structure) on side stream.
    cudaEventRecord(ctx.eFork, 0);
    cudaStreamWaitEvent(ctx.side, ctx.eFork, 0);
    gemm1_kernel<<<gblocks, 256, 81920, ctx.side>>>(feat, W1, n);
    cudaEventRecord(ctx.eJoin, ctx.side);

    // Main stream: degrees -> scan(+norms) -> CSR (hidden under gemm1).
    zero_kernel      <<<(n + B - 1) / B, B>>>(n);
    degree_kernel    <<<(E + B - 1) / B, B>>>(src, dst, E);
    scanA_norm_kernel<<<nb, SCAN_B>>>(n);
    scanB_kernel     <<<1, 256>>>(nb);
    scatter_kernel   <<<(E + B - 1) / B, B>>>(src, dst, E);

    // Join, then scale h by norm_out.
    cudaStreamWaitEvent(0, ctx.eJoin, 0);
    scale_h_kernel<<<(n * 8 + B - 1) / B, B>>>(n);

    gather0_kernel   <<<(n * 8 + B - 1) / B, B>>>(b1, n);
    mid_kernel       <<<gblocks, 256>>>(W2, n);
    gather_out_kernel<<<(n * 8 + B - 1) / B, B>>>(b2, out, n);
}

// round 9
// speedup vs baseline: 1.0819x; 1.0270x over previous
#include <cuda_runtime.h>
#include <cuda_fp16.h>
#include <cuda_bf16.h>

// GCN: 2-layer graph conv, N=100000, E=1.6M, 128 -> 32 -> 32.
// Round 9: gather restructure — 4 threads/dst (uint4 fp16 rows), unrolled
// multi-load groups, scale_h fused into gather0 (norm_out loaded per edge).
//   side stream : gemm1 (feat @ W1 -> g_hh fp16, UNSCALED)
//   main stream : zero -> degrees -> scanA(+norms) -> scanB -> scatter
//   join
//   gather0     : g_t = relu((sum g_hh[s]*norm_out[s]) * ni + b1)   [fp32]
//   mid         : g_hh2 = (g_t @ W2) * norm_out                     [fp16]
//   gather_out  : d_out = (sum g_hh2[s]) * ni + b2                  [fp32]

#define MAXN 100000
#define MAXE 1600000
#define SCAN_B 512

__device__ int    g_deg_out[MAXN];
__device__ int    g_deg_in[MAXN];
__device__ float  g_norm_out[MAXN];
__device__ float  g_norm_in[MAXN];
__device__ int    g_offset[MAXN];
__device__ int    g_cursor[MAXN];
__device__ int    g_csr[MAXE];
__device__ int    g_blocksums[(MAXN + SCAN_B - 1) / SCAN_B];
__device__ uint4  g_hh [MAXN * 4];     // fp16 h rows: 64B = 4 uint4 (16B aligned)
__device__ uint4  g_hh2[MAXN * 4];     // fp16 h2 rows
__device__ float4 g_t[MAXN * 8];       // layer-1 activations (fp32)

// ---- helpers ----
__device__ __forceinline__ uint2 pack_h4(float4 a) {
    __half2 lo = __floats2half2_rn(a.x, a.y);
    __half2 hi = __floats2half2_rn(a.z, a.w);
    uint2 u;
    u.x = *(const unsigned int*)&lo;
    u.y = *(const unsigned int*)&hi;
    return u;
}
// acc[0..7] += unpack8(u) * s
__device__ __forceinline__ void acc_h8(float* acc, uint4 u, float s) {
    float2 f0 = __half22float2(*(const __half2*)&u.x);
    float2 f1 = __half22float2(*(const __half2*)&u.y);
    float2 f2 = __half22float2(*(const __half2*)&u.z);
    float2 f3 = __half22float2(*(const __half2*)&u.w);
    acc[0] += f0.x * s; acc[1] += f0.y * s;
    acc[2] += f1.x * s; acc[3] += f1.y * s;
    acc[4] += f2.x * s; acc[5] += f2.y * s;
    acc[6] += f3.x * s; acc[7] += f3.y * s;
}

// ---------------------------------------------------------------- zero
__global__ void zero_kernel(int n) {
    int i = blockIdx.x * blockDim.x + threadIdx.x;
    if (i < n) { g_deg_out[i] = 0; g_deg_in[i] = 0; g_cursor[i] = 0; }
}

// ---------------------------------------------------------------- degrees
__global__ void degree_kernel(const int* __restrict__ src,
                              const int* __restrict__ dst, int E) {
    int e = blockIdx.x * blockDim.x + threadIdx.x;
    if (e < E) {
        atomicAdd(&g_deg_out[src[e]], 1);
        atomicAdd(&g_deg_in[dst[e]], 1);
    }
}

// ---------------------------------------------------------------- scanA + norms
__global__ __launch_bounds__(SCAN_B) void scanA_norm_kernel(int n) {
    __shared__ int swarp[16];
    int t = threadIdx.x;
    int i = blockIdx.x * SCAN_B + t;
    int v = 0;
    if (i < n) {
        int din = g_deg_in[i];
        v = din;
        g_norm_in[i]  = rsqrtf(fmaxf((float)din, 1.f));
        g_norm_out[i] = rsqrtf(fmaxf((float)g_deg_out[i], 1.f));
    }
    int lane = t & 31, w = t >> 5;
    int x = v;
    #pragma unroll
    for (int d = 1; d < 32; d <<= 1) {
        int y = __shfl_up_sync(0xffffffffu, x, d);
        if (lane >= d) x += y;
    }
    if (lane == 31) swarp[w] = x;
    __syncthreads();
    if (w == 0 && t < 16) {
        int y = swarp[t];
        #pragma unroll
        for (int d = 1; d < 16; d <<= 1) {
            int z = __shfl_up_sync(0xffffu, y, d);
            if (t >= d) y += z;
        }
        swarp[t] = y;
    }
    __syncthreads();
    int base = (w > 0) ? swarp[w - 1] : 0;
    int incl = x + base;
    if (i < n) g_offset[i] = incl - v;
    if (t == SCAN_B - 1) g_blocksums[blockIdx.x] = incl;
}

// ---------------------------------------------------------------- scanB
__global__ __launch_bounds__(256) void scanB_kernel(int nb) {
    __shared__ int swarp[8];
    int t = threadIdx.x;
    int v = (t < nb) ? g_blocksums[t] : 0;
    int lane = t & 31, w = t >> 5;
    int x = v;
    #pragma unroll
    for (int d = 1; d < 32; d <<= 1) {
        int y = __shfl_up_sync(0xffffffffu, x, d);
        if (lane >= d) x += y;
    }
    if (lane == 31) swarp[w] = x;
    __syncthreads();
    if (w == 0 && t < 8) {
        int y = swarp[t];
        #pragma unroll
        for (int d = 1; d < 8; d <<= 1) {
            int z = __shfl_up_sync(0xffu, y, d);
            if (t >= d) y += z;
        }
        swarp[t] = y;
    }
    __syncthreads();
    int base = (w > 0) ? swarp[w - 1] : 0;
    if (t < nb) g_blocksums[t] = x + base - v;
}

// ---------------------------------------------------------------- CSR scatter
__global__ void scatter_kernel(const int* __restrict__ src,
                               const int* __restrict__ dst, int E) {
    int e = blockIdx.x * blockDim.x + threadIdx.x;
    if (e < E) {
        int d = dst[e];
        int p = atomicAdd(&g_cursor[d], 1);
        g_csr[g_offset[d] + g_blocksums[d >> 9] + p] = src[e];
    }
}

// ---------------------------------------------------------------- GEMM1 (feat @ W1 -> fp16, UNSCALED)
__global__ __launch_bounds__(256) void gemm1_kernel(const float* __restrict__ feat,
                                                    const float* __restrict__ W1, int n) {
    extern __shared__ float4 dyn[];
    float4* sW = dyn;            // [k=128][cg=8]
    float4* sF = dyn + 1024;     // [row=128][k4=32] swizzled
    int t = threadIdx.x;

    for (int i = t; i < 1024; i += 256) sW[i] = ((const float4*)W1)[i];
    int row0 = blockIdx.x * 128;
    #pragma unroll
    for (int j = 0; j < 16; j++) {
        int i = t + j * 256;
        int r = i >> 5, k4 = i & 31;
        int gr = row0 + r;
        float4 v = make_float4(0.f, 0.f, 0.f, 0.f);
        if (gr < n) v = ((const float4*)feat)[gr * 32 + k4];
        sF[r * 32 + (k4 ^ (r & 7))] = v;
    }
    __syncthreads();

    int rt = t >> 3, cg = t & 7;
    int sw = rt & 7;
    const float4* fp0 = &sF[(rt +  0) * 32];
    const float4* fp1 = &sF[(rt + 32) * 32];
    const float4* fp2 = &sF[(rt + 64) * 32];
    const float4* fp3 = &sF[(rt + 96) * 32];

    float4 a0 = make_float4(0.f,0.f,0.f,0.f), a1 = a0, a2 = a0, a3 = a0;

    #pragma unroll 4
    for (int k4 = 0; k4 < 32; k4++) {
        float4 f0 = fp0[k4 ^ sw];
        float4 f1 = fp1[k4 ^ sw];
        float4 f2 = fp2[k4 ^ sw];
        float4 f3 = fp3[k4 ^ sw];
        #pragma unroll
        for (int i = 0; i < 4; i++) {
            float4 w = sW[(k4 * 4 + i) * 8 + cg];
            float c0 = (i == 0) ? f0.x : (i == 1) ? f0.y : (i == 2) ? f0.z : f0.w;
            float c1 = (i == 0) ? f1.x : (i == 1) ? f1.y : (i == 2) ? f1.z : f1.w;
            float c2 = (i == 0) ? f2.x : (i == 1) ? f2.y : (i == 2) ? f2.z : f2.w;
            float c3 = (i == 0) ? f3.x : (i == 1) ? f3.y : (i == 2) ? f3.z : f3.w;
            a0.x += c0*w.x; a0.y += c0*w.y; a0.z += c0*w.z; a0.w += c0*w.w;
            a1.x += c1*w.x; a1.y += c1*w.y; a1.z += c1*w.z; a1.w += c1*w.w;
            a2.x += c2*w.x; a2.y += c2*w.y; a2.z += c2*w.z; a2.w += c2*w.w;
            a3.x += c3*w.x; a3.y += c3*w.y; a3.z += c3*w.z; a3.w += c3*w.w;
        }
    }

    uint2* hh = (uint2*)g_hh;
    int gr;
    gr = row0 + rt;      if (gr < n) hh[gr * 8 + cg] = pack_h4(a0);
    gr = row0 + rt + 32; if (gr < n) hh[gr * 8 + cg] = pack_h4(a1);
    gr = row0 + rt + 64; if (gr < n) hh[gr * 8 + cg] = pack_h4(a2);
    gr = row0 + rt + 96; if (gr < n) hh[gr * 8 + cg] = pack_h4(a3);
}

// ---------------------------------------------------------------- gather0
// 4 threads/dst, each owns 8 columns (one uint4 of the 64B fp16 row).
// acc = sum_s h[s] * norm_out[s];  g_t = relu(acc*ni + b1).
__global__ __launch_bounds__(256) void gather0_kernel(const float* __restrict__ b1, int n) {
    int tid = blockIdx.x * blockDim.x + threadIdx.x;
    int d = tid >> 2;
    if (d >= n) return;
    int c = tid & 3;
    int j = g_offset[d] + g_blocksums[d >> 9];
    int e = j + g_deg_in[d];

    float acc[8] = {0.f, 0.f, 0.f, 0.f, 0.f, 0.f, 0.f, 0.f};
    for (; j + 3 < e; j += 4) {
        int s0 = __ldg(&g_csr[j]);
        int s1 = __ldg(&g_csr[j + 1]);
        int s2 = __ldg(&g_csr[j + 2]);
        int s3 = __ldg(&g_csr[j + 3]);
        float n0 = __ldg(&g_norm_out[s0]);
        float n1 = __ldg(&g_norm_out[s1]);
        float n2 = __ldg(&g_norm_out[s2]);
        float n3 = __ldg(&g_norm_out[s3]);
        uint4 u0 = g_hh[s0 * 4 + c];
        uint4 u1 = g_hh[s1 * 4 + c];
        uint4 u2 = g_hh[s2 * 4 + c];
        uint4 u3 = g_hh[s3 * 4 + c];
        acc_h8(acc, u0, n0);
        acc_h8(acc, u1, n1);
        acc_h8(acc, u2, n2);
        acc_h8(acc, u3, n3);
    }
    for (; j < e; j++) {
        int s0 = __ldg(&g_csr[j]);
        float n0 = __ldg(&g_norm_out[s0]);
        uint4 u0 = g_hh[s0 * 4 + c];
        acc_h8(acc, u0, n0);
    }

    float ni = g_norm_in[d];
    float4 bA = ((const float4*)b1)[c * 2];
    float4 bB = ((const float4*)b1)[c * 2 + 1];
    float4 tA, tB;
    tA.x = fmaxf(acc[0] * ni + bA.x, 0.f);
    tA.y = fmaxf(acc[1] * ni + bA.y, 0.f);
    tA.z = fmaxf(acc[2] * ni + bA.z, 0.f);
    tA.w = fmaxf(acc[3] * ni + bA.w, 0.f);
    tB.x = fmaxf(acc[4] * ni + bB.x, 0.f);
    tB.y = fmaxf(acc[5] * ni + bB.y, 0.f);
    tB.z = fmaxf(acc[6] * ni + bB.z, 0.f);
    tB.w = fmaxf(acc[7] * ni + bB.w, 0.f);
    g_t[d * 8 + c * 2]     = tA;
    g_t[d * 8 + c * 2 + 1] = tB;
}

// ---------------------------------------------------------------- mid GEMM (g_t @ W2 -> fp16, * norm_out)
__global__ __launch_bounds__(256) void mid_kernel(const float* __restrict__ W2, int n) {
    __shared__ float4 sW2[32 * 8];
    __shared__ float4 sT[128 * 8];
    int t = threadIdx.x;
    sW2[t] = ((const float4*)W2)[t];
    int row0 = blockIdx.x * 128;
    #pragma unroll
    for (int j = 0; j < 4; j++) {
        int i = t + j * 256;
        int r = i >> 3, k4 = i & 7;
        int gr = row0 + r;
        float4 v = make_float4(0.f, 0.f, 0.f, 0.f);
        if (gr < n) v = g_t[gr * 8 + k4];
        sT[r * 8 + (k4 ^ (r & 7))] = v;
    }
    __syncthreads();

    int rt = t >> 3, cg = t & 7;
    int sw = rt & 7;
    const float4* fp0 = &sT[(rt +  0) * 8];
    const float4* fp1 = &sT[(rt + 32) * 8];
    const float4* fp2 = &sT[(rt + 64) * 8];
    const float4* fp3 = &sT[(rt + 96) * 8];

    float4 a0 = make_float4(0.f,0.f,0.f,0.f), a1 = a0, a2 = a0, a3 = a0;

    #pragma unroll
    for (int k4 = 0; k4 < 8; k4++) {
        float4 f0 = fp0[k4 ^ sw];
        float4 f1 = fp1[k4 ^ sw];
        float4 f2 = fp2[k4 ^ sw];
        float4 f3 = fp3[k4 ^ sw];
        #pragma unroll
        for (int i = 0; i < 4; i++) {
            float4 w = sW2[(k4 * 4 + i) * 8 + cg];
            float c0 = (i == 0) ? f0.x : (i == 1) ? f0.y : (i == 2) ? f0.z : f0.w;
            float c1 = (i == 0) ? f1.x : (i == 1) ? f1.y : (i == 2) ? f1.z : f1.w;
            float c2 = (i == 0) ? f2.x : (i == 1) ? f2.y : (i == 2) ? f2.z : f2.w;
            float c3 = (i == 0) ? f3.x : (i == 1) ? f3.y : (i == 2) ? f3.z : f3.w;
            a0.x += c0*w.x; a0.y += c0*w.y; a0.z += c0*w.z; a0.w += c0*w.w;
            a1.x += c1*w.x; a1.y += c1*w.y; a1.z += c1*w.z; a1.w += c1*w.w;
            a2.x += c2*w.x; a2.y += c2*w.y; a2.z += c2*w.z; a2.w += c2*w.w;
            a3.x += c3*w.x; a3.y += c3*w.y; a3.z += c3*w.z; a3.w += c3*w.w;
        }
    }

    uint2* hh2 = (uint2*)g_hh2;
    #pragma unroll
    for (int j = 0; j < 4; j++) {
        int gr = row0 + rt + 32 * j;
        if (gr < n) {
            float ns = g_norm_out[gr];
            float4 a = (j == 0) ? a0 : (j == 1) ? a1 : (j == 2) ? a2 : a3;
            a.x *= ns; a.y *= ns; a.z *= ns; a.w *= ns;
            hh2[gr * 8 + cg] = pack_h4(a);
        }
    }
}

// ---------------------------------------------------------------- gather -> output
// 4 threads/dst; out[d] = (sum g_hh2[s]) * ni + b2   (h2 pre-scaled by norm_out)
__global__ __launch_bounds__(256) void gather_out_kernel(const float* __restrict__ b2,
                                                         float4* __restrict__ outp, int n) {
    int tid = blockIdx.x * blockDim.x + threadIdx.x;
    int d = tid >> 2;
    if (d >= n) return;
    int c = tid & 3;
    int j = g_offset[d] + g_blocksums[d >> 9];
    int e = j + g_deg_in[d];

    float acc[8] = {0.f, 0.f, 0.f, 0.f, 0.f, 0.f, 0.f, 0.f};
    for (; j + 3 < e; j += 4) {
        int s0 = __ldg(&g_csr[j]);
        int s1 = __ldg(&g_csr[j + 1]);
        int s2 = __ldg(&g_csr[j + 2]);
        int s3 = __ldg(&g_csr[j + 3]);
        uint4 u0 = g_hh2[s0 * 4 + c];
        uint4 u1 = g_hh2[s1 * 4 + c];
        uint4 u2 = g_hh2[s2 * 4 + c];
        uint4 u3 = g_hh2[s3 * 4 + c];
        acc_h8(acc, u0, 1.f);
        acc_h8(acc, u1, 1.f);
        acc_h8(acc, u2, 1.f);
        acc_h8(acc, u3, 1.f);
    }
    for (; j < e; j++) {
        int s0 = __ldg(&g_csr[j]);
        uint4 u0 = g_hh2[s0 * 4 + c];
        acc_h8(acc, u0, 1.f);
    }

    float ni = g_norm_in[d];
    float4 bA = ((const float4*)b2)[c * 2];
    float4 bB = ((const float4*)b2)[c * 2 + 1];
    float4 oA, oB;
    oA.x = acc[0] * ni + bA.x;
    oA.y = acc[1] * ni + bA.y;
    oA.z = acc[2] * ni + bA.z;
    oA.w = acc[3] * ni + bA.w;
    oB.x = acc[4] * ni + bB.x;
    oB.y = acc[5] * ni + bB.y;
    oB.z = acc[6] * ni + bB.z;
    oB.w = acc[7] * ni + bB.w;
    outp[d * 8 + c * 2]     = oA;
    outp[d * 8 + c * 2 + 1] = oB;
}

// ---------------------------------------------------------------- launch
namespace {
struct Ctx {
    cudaStream_t side;
    cudaEvent_t eFork, eJoin;
    Ctx() {
        cudaStreamCreateWithFlags(&side, cudaStreamNonBlocking);
        cudaEventCreateWithFlags(&eFork, cudaEventDisableTiming);
        cudaEventCreateWithFlags(&eJoin, cudaEventDisableTiming);
        cudaFuncSetAttribute(gemm1_kernel,
                             cudaFuncAttributeMaxDynamicSharedMemorySize, 81920);
    }
};
}

extern "C" void kernel_launch(void* const* d_in, const int* in_sizes, int n_in,
                              void* d_out, int out_size) {
    static Ctx ctx;   // resource init only (streams/events/attr), no cached work

    const float* feat = (const float*)d_in[0];
    const float* W1   = (const float*)d_in[1];
    const float* b1   = (const float*)d_in[2];
    const float* W2   = (const float*)d_in[3];
    const float* b2   = (const float*)d_in[4];
    const int*   src  = (const int*)d_in[5];
    const int*   dst  = (const int*)d_in[6];
    float4* out = (float4*)d_out;

    int n = in_sizes[0] / 128;
    int E = in_sizes[5];

    const int B = 256;
    int gblocks = (n + 127) / 128;
    int nb = (n + SCAN_B - 1) / SCAN_B;

    // Fork: gemm1 (independent of graph structure) on side stream.
    cudaEventRecord(ctx.eFork, 0);
    cudaStreamWaitEvent(ctx.side, ctx.eFork, 0);
    gemm1_kernel<<<gblocks, 256, 81920, ctx.side>>>(feat, W1, n);
    cudaEventRecord(ctx.eJoin, ctx.side);

    // Main stream: degrees -> scan(+norms) -> CSR (hidden under gemm1).
    zero_kernel      <<<(n + B - 1) / B, B>>>(n);
    degree_kernel    <<<(E + B - 1) / B, B>>>(src, dst, E);
    scanA_norm_kernel<<<nb, SCAN_B>>>(n);
    scanB_kernel     <<<1, 256>>>(nb);
    scatter_kernel   <<<(E + B - 1) / B, B>>>(src, dst, E);

    // Join: gather0 needs g_hh (gemm1) + norms/CSR (main chain).
    cudaStreamWaitEvent(0, ctx.eJoin, 0);

    gather0_kernel   <<<(n * 4 + B - 1) / B, B>>>(b1, n);
    mid_kernel       <<<gblocks, 256>>>(W2, n);
    gather_out_kernel<<<(n * 4 + B - 1) / B, B>>>(b2, out, n);
}